// round 17
// baseline (speedup 1.0000x reference)
#include <cuda_runtime.h>
#include <cuda_fp16.h>
#include <cstdint>

#define NN 100000
#define NE 1600000
#define NG 1000
#define NB 98              // scan blocks: 98 * 1024 >= NN

// ---------------- scratch (device globals; 16B-aligned) --------------------
__device__ __align__(16) __half g_P16[NN * 64];   // fp16 layer activations (GEMM input)
__device__ __align__(16) float  g_Z[NN * 64];     // fp32 GEMM output (self term)
__device__ __align__(16) __half g_Z16[NN * 64];   // fp16 GEMM output (messages)
__device__ __align__(16) float  g_Pa[NN * 64];    // fp32 layer-3 output (pool input)
__device__ __align__(16) __half g_W1h[128 * 64];
__device__ __align__(16) __half g_W2h[64 * 64];
__device__ __align__(16) __half g_W3h[64 * 64];
__device__ __align__(16) int g_deg[NN];
__device__ int g_rowstart[NN];
__device__ int g_cursor[NN];
__device__ int g_srclist[NE];
__device__ int g_bsum[128];

template <int S> __device__ __forceinline__ const __half* w16_buf();
template <> __device__ __forceinline__ const __half* w16_buf<0>() { return g_W1h; }
template <> __device__ __forceinline__ const __half* w16_buf<1>() { return g_W2h; }
template <> __device__ __forceinline__ const __half* w16_buf<2>() { return g_W3h; }

// ---------------- half2 <-> uint bit-casts ----------------------------------
__device__ __forceinline__ unsigned h2_to_u(__half2 h) {
    __half2_raw r = *reinterpret_cast<__half2_raw*>(&h);
    return (unsigned)r.x | ((unsigned)r.y << 16);
}
__device__ __forceinline__ __half2 u_to_h2(unsigned u) {
    __half2_raw r;
    r.x = (unsigned short)(u & 0xFFFF);
    r.y = (unsigned short)(u >> 16);
    return *reinterpret_cast<__half2*>(&r);
}
__device__ __forceinline__ unsigned f2_to_h2u(float a, float b) {
    return h2_to_u(__float22half2_rn(make_float2(a, b)));
}
__device__ __forceinline__ uint32_t smem_u32(const void* p) {
    uint32_t r;
    asm("{ .reg .u64 t; cvta.to.shared.u64 t, %1; cvt.u32.u64 %0, t; }"
        : "=r"(r) : "l"(p));
    return r;
}

// ---------------- converts --------------------------------------------------
__global__ void __launch_bounds__(256) convert_w_kernel(
    const float* __restrict__ W1, const float* __restrict__ W2,
    const float* __restrict__ W3) {
    int i = blockIdx.x * 256 + threadIdx.x;
    if (i < 128 * 64) g_W1h[i] = __float2half_rn(W1[i]);
    else if (i < 128 * 64 + 64 * 64) g_W2h[i - 128 * 64] = __float2half_rn(W2[i - 128 * 64]);
    else if (i < 128 * 64 + 2 * 64 * 64) g_W3h[i - 128 * 64 - 64 * 64] = __float2half_rn(W3[i - 128 * 64 - 64 * 64]);
}

// ---------------- CSR build (edge_index is int32) --------------------------
__global__ void zero_deg_kernel() {
    int i = blockIdx.x * 256 + threadIdx.x;
    if (i < NN) g_deg[i] = 0;
}

__global__ void __launch_bounds__(256) count_deg_kernel(const int* __restrict__ ei) {
    int t = blockIdx.x * 256 + threadIdx.x;
    if (t * 4 >= NE) return;
    int4 d4 = ((const int4*)(ei + NE))[t];
    if ((unsigned)d4.x < NN) atomicAdd(&g_deg[d4.x], 1);
    if ((unsigned)d4.y < NN) atomicAdd(&g_deg[d4.y], 1);
    if ((unsigned)d4.z < NN) atomicAdd(&g_deg[d4.z], 1);
    if ((unsigned)d4.w < NN) atomicAdd(&g_deg[d4.w], 1);
}

__global__ void __launch_bounds__(256) scanA_kernel() {
    __shared__ int red[256];
    int t = threadIdx.x;
    int base = blockIdx.x * 1024 + t * 4;
    int s = 0;
#pragma unroll
    for (int i = 0; i < 4; i++) {
        int idx = base + i;
        if (idx < NN) s += g_deg[idx];
    }
    red[t] = s;
    __syncthreads();
    for (int off = 128; off > 0; off >>= 1) {
        if (t < off) red[t] += red[t + off];
        __syncthreads();
    }
    if (t == 0) g_bsum[blockIdx.x] = red[0];
}

__global__ void __launch_bounds__(256) scanC_kernel() {
    __shared__ int offsh[256];
    __shared__ int sh[256];
    int t = threadIdx.x;

    offsh[t] = (t < blockIdx.x) ? g_bsum[t] : 0;
    int base = blockIdx.x * 1024 + t * 4;
    int d[4];
    int s = 0;
#pragma unroll
    for (int i = 0; i < 4; i++) {
        int idx = base + i;
        d[i] = (idx < NN) ? g_deg[idx] : 0;
        s += d[i];
    }
    sh[t] = s;
    __syncthreads();
    for (int off = 128; off > 0; off >>= 1) {
        if (t < off) offsh[t] += offsh[t + off];
        __syncthreads();
    }
    for (int off = 1; off < 256; off <<= 1) {
        int v = sh[t];
        int u = (t >= off) ? sh[t - off] : 0;
        __syncthreads();
        sh[t] = v + u;
        __syncthreads();
    }
    int run = offsh[0] + ((t == 0) ? 0 : sh[t - 1]);
#pragma unroll
    for (int i = 0; i < 4; i++) {
        int idx = base + i;
        if (idx < NN) {
            g_rowstart[idx] = run;
            g_cursor[idx] = run;
            run += d[i];
        }
    }
}

__global__ void __launch_bounds__(256) fill_csr_kernel(const int* __restrict__ ei) {
    int t = blockIdx.x * 256 + threadIdx.x;
    if (t * 4 >= NE) return;
    int4 s4 = ((const int4*)ei)[t];
    int4 d4 = ((const int4*)(ei + NE))[t];
    int s[4] = {s4.x, s4.y, s4.z, s4.w};
    int d[4] = {d4.x, d4.y, d4.z, d4.w};
#pragma unroll
    for (int i = 0; i < 4; i++) {
        if ((unsigned)s[i] < NN && (unsigned)d[i] < NN) {
            int pos = atomicAdd(&g_cursor[d[i]], 1);
            if ((unsigned)pos < NE) g_srclist[pos] = s[i];
        }
    }
}

// ---------------- GEMM via HMMA: Z = A(fp16) @ W(fp16), fp32 accum ---------
// 4 warps x 32 rows = 128 rows/block, 64 cols. Per warp per k16:
//   2x ldmatrix.x4 (A, 16 rows each) + 4x ldmatrix.x4.trans (B, 2 n-tiles each)
//   + 16 mma  -> 3x fewer smem ops per output than the 8-warp/16-row version.
// ASEL=0 converts fp32 x -> fp16 during the smem fill (no separate convert pass).
template <int K, int ASEL, int WSEL>
__global__ void __launch_bounds__(128) gemm_mma_kernel(const float* __restrict__ xext) {
    constexpr int CPR = K / 8;                 // 16B chunks per A row
    __shared__ uint4 As[128 * CPR];            // swizzled A tile
    __shared__ uint4 Ws[K * 8];                // swizzled W (64 cols = 8 chunks/row)

    const uint4* Wg = (const uint4*)w16_buf<WSEL>();

    int tid = threadIdx.x;
    int row0 = blockIdx.x * 128;

    // cooperative fills (coalesced), swizzle: chunk ^= (row & 7)
    if (ASEL == 0) {
        for (int i = tid; i < 128 * CPR; i += 128) {
            int r = i / CPR, c = i % CPR;
            int gr = row0 + r;
            uint4 v = make_uint4(0u, 0u, 0u, 0u);
            if (gr < NN) {
                const float4* p = (const float4*)(xext + (long long)gr * K + c * 8);
                float4 v0 = p[0], v1 = p[1];
                v.x = f2_to_h2u(v0.x, v0.y);
                v.y = f2_to_h2u(v0.z, v0.w);
                v.z = f2_to_h2u(v1.x, v1.y);
                v.w = f2_to_h2u(v1.z, v1.w);
            }
            As[r * CPR + (c ^ (r & 7))] = v;
        }
    } else {
        const uint4* Ag = (const uint4*)g_P16;
        for (int i = tid; i < 128 * CPR; i += 128) {
            int r = i / CPR, c = i % CPR;
            int gr = row0 + r;
            uint4 v = make_uint4(0u, 0u, 0u, 0u);
            if (gr < NN) v = Ag[gr * CPR + c];
            As[r * CPR + (c ^ (r & 7))] = v;
        }
    }
    for (int i = tid; i < K * 8; i += 128) {
        int k = i / 8, c = i % 8;
        Ws[k * 8 + (c ^ (k & 7))] = Wg[i];
    }
    __syncthreads();

    int wid = tid >> 5, lane = tid & 31;
    int wrow = wid * 32;                       // 32 local rows per warp

    float acc[2][8][4];
#pragma unroll
    for (int h = 0; h < 2; h++)
#pragma unroll
        for (int t = 0; t < 8; t++)
#pragma unroll
            for (int j = 0; j < 4; j++) acc[h][t][j] = 0.0f;

    uint32_t As_base = smem_u32(As);
    uint32_t Ws_base = smem_u32(Ws);

#pragma unroll
    for (int k16 = 0; k16 < K / 16; k16++) {
        int kc = k16 * 2 + (lane >> 4);        // 16B chunk within A row
        uint32_t a[2][4];
#pragma unroll
        for (int h = 0; h < 2; h++) {
            int ar = wrow + h * 16 + (lane & 15);
            uint32_t aaddr = As_base + (ar * CPR + (kc ^ (ar & 7))) * 16;
            asm volatile("ldmatrix.sync.aligned.m8n8.x4.shared.b16 {%0,%1,%2,%3}, [%4];"
                         : "=r"(a[h][0]), "=r"(a[h][1]), "=r"(a[h][2]), "=r"(a[h][3])
                         : "r"(aaddr));
        }
        int kk = k16 * 16 + (lane & 15);       // W row for this lane's B address
#pragma unroll
        for (int ntp = 0; ntp < 4; ntp++) {
            int chunk = ntp * 2 + (lane >> 4); // lanes 0-15: n-tile 2*ntp, 16-31: 2*ntp+1
            uint32_t baddr = Ws_base + (kk * 8 + (chunk ^ (kk & 7))) * 16;
            uint32_t b0, b1, b2, b3;
            asm volatile("ldmatrix.sync.aligned.m8n8.x4.trans.shared.b16 {%0,%1,%2,%3}, [%4];"
                         : "=r"(b0), "=r"(b1), "=r"(b2), "=r"(b3) : "r"(baddr));
#pragma unroll
            for (int h = 0; h < 2; h++) {
                asm volatile("mma.sync.aligned.m16n8k16.row.col.f32.f16.f16.f32 "
                             "{%0,%1,%2,%3}, {%4,%5,%6,%7}, {%8,%9}, {%0,%1,%2,%3};"
                             : "+f"(acc[h][2 * ntp][0]), "+f"(acc[h][2 * ntp][1]),
                               "+f"(acc[h][2 * ntp][2]), "+f"(acc[h][2 * ntp][3])
                             : "r"(a[h][0]), "r"(a[h][1]), "r"(a[h][2]), "r"(a[h][3]),
                               "r"(b0), "r"(b1));
                asm volatile("mma.sync.aligned.m16n8k16.row.col.f32.f16.f16.f32 "
                             "{%0,%1,%2,%3}, {%4,%5,%6,%7}, {%8,%9}, {%0,%1,%2,%3};"
                             : "+f"(acc[h][2 * ntp + 1][0]), "+f"(acc[h][2 * ntp + 1][1]),
                               "+f"(acc[h][2 * ntp + 1][2]), "+f"(acc[h][2 * ntp + 1][3])
                             : "r"(a[h][0]), "r"(a[h][1]), "r"(a[h][2]), "r"(a[h][3]),
                               "r"(b2), "r"(b3));
            }
        }
    }

    // epilogue: lane -> (row = lane>>2 [+8], col = (lane&3)*2) per n-tile
    int col = (lane & 3) * 2;
#pragma unroll
    for (int h = 0; h < 2; h++) {
        int gr0 = row0 + wrow + h * 16 + (lane >> 2);
        int gr1 = gr0 + 8;
#pragma unroll
        for (int nt = 0; nt < 8; nt++) {
            int cc = nt * 8 + col;
            if (gr0 < NN) {
                *(float2*)(g_Z + gr0 * 64 + cc) = make_float2(acc[h][nt][0], acc[h][nt][1]);
                *(unsigned*)((__half*)g_Z16 + gr0 * 64 + cc) = f2_to_h2u(acc[h][nt][0], acc[h][nt][1]);
            }
            if (gr1 < NN) {
                *(float2*)(g_Z + gr1 * 64 + cc) = make_float2(acc[h][nt][2], acc[h][nt][3]);
                *(unsigned*)((__half*)g_Z16 + gr1 * 64 + cc) = f2_to_h2u(acc[h][nt][2], acc[h][nt][3]);
            }
        }
    }
}

// ---- gather: P[n] = relu((1+eps)*Z[n](fp32) + b + sum_in Z16[src](fp16)) --
// 8 threads per node; uint4 fp16 lanes; ILP-4 (the proven config).
// OUT16=1 -> fp16 g_P16 (next GEMM input); OUT16=0 -> fp32 g_Pa (pool input).
template <int OUT16>
__global__ void __launch_bounds__(256) gather_kernel(
    const float* __restrict__ b, const float* __restrict__ epsp)
{
    int gid = blockIdx.x * 256 + threadIdx.x;
    int n = gid >> 3;
    int lane = gid & 7;
    if (n >= NN) return;

    const float4* Z4 = (const float4*)g_Z;
    const uint4*  H4 = (const uint4*)g_Z16;
    float ep = 1.0f + *epsp;
    const float* bp = b + lane * 8;

    float4 z0 = Z4[n * 16 + lane * 2];
    float4 z1 = Z4[n * 16 + lane * 2 + 1];
    float a0 = fmaf(ep, z0.x, bp[0]);
    float a1 = fmaf(ep, z0.y, bp[1]);
    float a2 = fmaf(ep, z0.z, bp[2]);
    float a3 = fmaf(ep, z0.w, bp[3]);
    float a4 = fmaf(ep, z1.x, bp[4]);
    float a5 = fmaf(ep, z1.y, bp[5]);
    float a6 = fmaf(ep, z1.z, bp[6]);
    float a7 = fmaf(ep, z1.w, bp[7]);

    int beg = g_rowstart[n];
    int end = beg + g_deg[n];
    int k = beg;
    for (; k + 4 <= end; k += 4) {
        int s0 = g_srclist[k];
        int s1 = g_srclist[k + 1];
        int s2 = g_srclist[k + 2];
        int s3 = g_srclist[k + 3];
        uint4 h0 = H4[s0 * 8 + lane];
        uint4 h1 = H4[s1 * 8 + lane];
        uint4 h2 = H4[s2 * 8 + lane];
        uint4 h3 = H4[s3 * 8 + lane];
#pragma unroll
        for (int i = 0; i < 4; i++) {
            uint4 h = (i == 0) ? h0 : (i == 1) ? h1 : (i == 2) ? h2 : h3;
            float2 f0 = __half22float2(u_to_h2(h.x));
            float2 f1 = __half22float2(u_to_h2(h.y));
            float2 f2 = __half22float2(u_to_h2(h.z));
            float2 f3 = __half22float2(u_to_h2(h.w));
            a0 += f0.x; a1 += f0.y; a2 += f1.x; a3 += f1.y;
            a4 += f2.x; a5 += f2.y; a6 += f3.x; a7 += f3.y;
        }
    }
    for (; k < end; k++) {
        int s = g_srclist[k];
        uint4 h = H4[s * 8 + lane];
        float2 f0 = __half22float2(u_to_h2(h.x));
        float2 f1 = __half22float2(u_to_h2(h.y));
        float2 f2 = __half22float2(u_to_h2(h.z));
        float2 f3 = __half22float2(u_to_h2(h.w));
        a0 += f0.x; a1 += f0.y; a2 += f1.x; a3 += f1.y;
        a4 += f2.x; a5 += f2.y; a6 += f3.x; a7 += f3.y;
    }

    a0 = fmaxf(a0, 0.0f); a1 = fmaxf(a1, 0.0f);
    a2 = fmaxf(a2, 0.0f); a3 = fmaxf(a3, 0.0f);
    a4 = fmaxf(a4, 0.0f); a5 = fmaxf(a5, 0.0f);
    a6 = fmaxf(a6, 0.0f); a7 = fmaxf(a7, 0.0f);

    if (OUT16) {
        uint4 h;
        h.x = f2_to_h2u(a0, a1);
        h.y = f2_to_h2u(a2, a3);
        h.z = f2_to_h2u(a4, a5);
        h.w = f2_to_h2u(a6, a7);
        ((uint4*)g_P16)[n * 8 + lane] = h;
    } else {
        float4* P4 = (float4*)g_Pa;
        P4[n * 16 + lane * 2] = make_float4(a0, a1, a2, a3);
        P4[n * 16 + lane * 2 + 1] = make_float4(a4, a5, a6, a7);
    }
}

// ---------------- pool (batch sorted int32) + MLP head ---------------------
__global__ void __launch_bounds__(64) pool_head_kernel(
    const int* __restrict__ batch,
    const float* __restrict__ Wf, const float* __restrict__ bf,
    const float* __restrict__ Wl, const float* __restrict__ bl,
    float* __restrict__ out)
{
    int g = blockIdx.x;
    int t = threadIdx.x;

    int lo = 0, hi = NN;
    while (lo < hi) { int m = (lo + hi) >> 1; if (batch[m] < g) lo = m + 1; else hi = m; }
    int beg = lo;
    lo = beg; hi = NN;
    while (lo < hi) { int m = (lo + hi) >> 1; if (batch[m] < g + 1) lo = m + 1; else hi = m; }
    int end = lo;

    float s = 0.0f;
    for (int n = beg; n < end; n++)
        s += g_Pa[(long long)n * 64 + t];
    float cnt = (float)(end - beg);
    float pooled = s / fmaxf(cnt, 1.0f);

    __shared__ float ps[64];
    __shared__ float ts[10];
    ps[t] = pooled;
    __syncthreads();

    if (t < 10) {
        float acc = bf[t];
        for (int j = 0; j < 64; j++)
            acc = fmaf(ps[j], Wf[j * 10 + t], acc);
        ts[t] = fmaxf(acc, 0.0f);
    }
    __syncthreads();

    if (t == 0) {
        float r = bl[0];
#pragma unroll
        for (int o = 0; o < 10; o++) r = fmaf(ts[o], Wl[o], r);
        out[g] = r;
    }
}

// ---------------- launch ---------------------------------------------------
// gemm1 at launch index 3 = the profiler's fixed capture slot.
extern "C" void kernel_launch(void* const* d_in, const int* in_sizes, int n_in,
                              void* d_out, int out_size)
{
    const float* x     = (const float*)d_in[0];
    const int*   ei    = (const int*)d_in[1];     // int32 (JAX x64 disabled)
    const int*   batch = (const int*)d_in[2];     // int32, sorted
    const float* W1 = (const float*)d_in[3];
    const float* b1 = (const float*)d_in[4];
    const float* W2 = (const float*)d_in[5];
    const float* b2 = (const float*)d_in[6];
    const float* W3 = (const float*)d_in[7];
    const float* b3 = (const float*)d_in[8];
    const float* Wf = (const float*)d_in[9];
    const float* bf = (const float*)d_in[10];
    const float* Wl = (const float*)d_in[11];
    const float* bl = (const float*)d_in[12];
    const float* e1 = (const float*)d_in[13];
    const float* e2 = (const float*)d_in[14];
    const float* e3 = (const float*)d_in[15];
    float* out = (float*)d_out;

    const int node_grid  = (NN + 255) / 256;           // 391
    const int gemm_grid  = (NN + 127) / 128;           // 782
    const int edge4_grid = (NE / 4 + 255) / 256;       // 1563
    const int gath_grid  = (NN * 8 + 255) / 256;       // 3125

    convert_w_kernel<<<64, 256>>>(W1, W2, W3);                   // 0
    zero_deg_kernel<<<node_grid, 256>>>();                       // 1
    count_deg_kernel<<<edge4_grid, 256>>>(ei);                   // 2
    gemm_mma_kernel<128, 0, 0><<<gemm_grid, 128>>>(x);           // 3 <- profiled
    scanA_kernel<<<NB, 256>>>();                                 // 4
    scanC_kernel<<<NB, 256>>>();                                 // 5
    fill_csr_kernel<<<edge4_grid, 256>>>(ei);                    // 6

    // Layer 1 aggregate -> fp16 P16
    gather_kernel<1><<<gath_grid, 256>>>(b1, e1);

    // Layer 2
    gemm_mma_kernel<64, 1, 1><<<gemm_grid, 128>>>(nullptr);
    gather_kernel<1><<<gath_grid, 256>>>(b2, e2);

    // Layer 3 -> fp32 Pa for pooling
    gemm_mma_kernel<64, 1, 2><<<gemm_grid, 128>>>(nullptr);
    gather_kernel<0><<<gath_grid, 256>>>(b3, e3);

    // Mean-pool Pa per graph + head MLP
    pool_head_kernel<<<NG, 64>>>(batch, Wf, bf, Wl, bl, out);
}